// round 2
// baseline (speedup 1.0000x reference)
#include <cuda_runtime.h>
#include <cuda_bf16.h>

#define DAMPING_PARAM 0.7f

__global__ void zero_out_kernel(float4* __restrict__ out, int n4) {
    int i = blockIdx.x * blockDim.x + threadIdx.x;
    if (i < n4) out[i] = make_float4(0.f, 0.f, 0.f, 0.f);
}

__global__ __launch_bounds__(256) void electric_field_kernel(
    const int* __restrict__ edge_src,
    const int* __restrict__ edge_dst,
    const float* __restrict__ distances,
    const float* __restrict__ vec,
    const float* __restrict__ charges,
    const float* __restrict__ polarisability,
    float* __restrict__ out,
    int n_edges)
{
    int e = blockIdx.x * blockDim.x + threadIdx.x;
    if (e >= n_edges) return;

    int src = edge_src[e];
    int dst = edge_dst[e];
    float r = distances[e];

    float q  = __ldg(&charges[dst]);
    float pa = __ldg(&polarisability[src]);
    float pb = __ldg(&polarisability[dst]);

    float alpha = pa * pb;
    // u = r * alpha^(-1/6)
    float u = r * __expf(-__logf(alpha) * (1.0f / 6.0f));
    // damping = 1 - exp(-0.7 * u^1.5)
    float u15 = u * __fsqrt_rn(u);
    float damping = 1.0f - __expf(-DAMPING_PARAM * u15);
    // coeff = -q * damping / r^3
    float inv_r = __fdividef(1.0f, r);
    float coeff = -q * damping * inv_r * inv_r * inv_r;

    float vx = vec[3 * e + 0];
    float vy = vec[3 * e + 1];
    float vz = vec[3 * e + 2];

    float* o = out + 3 * src;
    atomicAdd(o + 0, coeff * vx);
    atomicAdd(o + 1, coeff * vy);
    atomicAdd(o + 2, coeff * vz);
}

extern "C" void kernel_launch(void* const* d_in, const int* in_sizes, int n_in,
                              void* d_out, int out_size) {
    // inputs: species[N], edge_src[E], edge_dst[E], distances[E], vec[E*3],
    //         charges[N], polarisability[N]
    const int*   edge_src = (const int*)d_in[1];
    const int*   edge_dst = (const int*)d_in[2];
    const float* dist     = (const float*)d_in[3];
    const float* vec      = (const float*)d_in[4];
    const float* charges  = (const float*)d_in[5];
    const float* pol      = (const float*)d_in[6];
    float* out = (float*)d_out;

    int n_edges = in_sizes[1];

    int n4 = out_size / 4;  // out_size = 300000, divisible by 4
    zero_out_kernel<<<(n4 + 255) / 256, 256>>>((float4*)out, n4);

    electric_field_kernel<<<(n_edges + 255) / 256, 256>>>(
        edge_src, edge_dst, dist, vec, charges, pol, out, n_edges);
}